// round 17
// baseline (speedup 1.0000x reference)
#include <cuda_runtime.h>

// out[b] = -(inp[b,:] . quad)^2 + inp[b,:] . linw + bias
// B = 16384, D = 4096, fp32. 256 MiB streaming read.
//
// R17: smem weights + deferred reduction + 8-wide load batches (untested
// combination). Register-resident weights cost 32 regs and cap the per-row
// x batch at 4 LDG.128 (the 64-reg / 4-blocks-per-SM cliff). Moving weights
// to smem frees those regs for an 8-wide batch: each warp owns a 1024-float
// chunk (4 warps per row; 8 warps process 2 rows per step), keeping 8
// independent LDG.128 in flight per warp — per-SM in-flight bytes double.
// LDS weight reads sit in the FMA section, off the load-issue path,
// conflict-free. smem = 32KB weights + 16KB partials = 48KB -> 4 blocks/SM.

#ifndef D_DIM
#define D_DIM 4096
#endif

constexpr int THREADS        = 256;             // 8 warps
constexpr int ROWS_PER_BLOCK = 16;
constexpr int ROW_F4         = D_DIM / 4;       // 1024 float4 per row
constexpr int CHUNK_F4       = 256;             // float4 per warp chunk (1024 floats)
constexpr int F4_PER_LANE    = CHUNK_F4 / 32;   // 8
constexpr int WARPS_PER_ROW  = ROW_F4 / CHUNK_F4;  // 4
constexpr int ROW_GROUPS     = 2;               // 8 warps / 4 warps-per-row

__global__ __launch_bounds__(THREADS)
void skinny_quad_kernel(const float* __restrict__ inp,
                        const float* __restrict__ quad,
                        const float* __restrict__ linw,
                        const float* __restrict__ linb,
                        float* __restrict__ out,
                        int B)
{
    __shared__ float4 s_wq[ROW_F4];                        // 16 KB
    __shared__ float4 s_wl[ROW_F4];                        // 16 KB
    __shared__ float2 s_part[ROWS_PER_BLOCK][WARPS_PER_ROW * 32];  // 16 KB

    const int tid  = threadIdx.x;
    const int lane = tid & 31;
    const int warp = tid >> 5;
    const int chunk = warp & (WARPS_PER_ROW - 1);   // 0..3
    const int rgrp  = warp >> 2;                    // 0..1
    const int cbase = chunk * CHUNK_F4;             // float4 base in row

    // Stage weights into smem (once per block)
    const float4* __restrict__ gq = reinterpret_cast<const float4*>(quad);
    const float4* __restrict__ gl = reinterpret_cast<const float4*>(linw);
    #pragma unroll
    for (int i = tid; i < ROW_F4; i += THREADS) {
        s_wq[i] = gq[i];
        s_wl[i] = gl[i];
    }
    __syncthreads();

    const int row0 = blockIdx.x * ROWS_PER_BLOCK;

    #pragma unroll 2
    for (int rr = 0; rr < ROWS_PER_BLOCK; rr += ROW_GROUPS) {
        const int r = rr + rgrp;                    // this warp's row in the pair
        const float4* __restrict__ xr =
            reinterpret_cast<const float4*>(inp + (size_t)(row0 + r) * D_DIM) + cbase;

        // 8 independent 128-bit streaming loads (4KB contiguous per warp-row)
        float4 x[F4_PER_LANE];
        #pragma unroll
        for (int i = 0; i < F4_PER_LANE; ++i)
            x[i] = __ldcs(&xr[i * 32 + lane]);

        float sq = 0.f, sl = 0.f;
        #pragma unroll
        for (int i = 0; i < F4_PER_LANE; ++i) {
            const float4 q = s_wq[cbase + i * 32 + lane];
            const float4 l = s_wl[cbase + i * 32 + lane];
            sq = fmaf(x[i].x, q.x, sq);
            sq = fmaf(x[i].y, q.y, sq);
            sq = fmaf(x[i].z, q.z, sq);
            sq = fmaf(x[i].w, q.w, sq);
            sl = fmaf(x[i].x, l.x, sl);
            sl = fmaf(x[i].y, l.y, sl);
            sl = fmaf(x[i].z, l.z, sl);
            sl = fmaf(x[i].w, l.w, sl);
        }

        // fire-and-forget per-lane partial; nothing else in the stream loop
        s_part[r][chunk * 32 + lane] = make_float2(sq, sl);
    }

    __syncthreads();

    // Block-wide reduction: 16 threads per row, each sums 8 of the 128
    // per-lane partials, then a 4-stage shuffle reduce in the 16-group.
    {
        const int row = tid >> 4;        // 0..15
        const int sub = tid & 15;        // 0..15

        float sq = 0.f, sl = 0.f;
        #pragma unroll
        for (int k = 0; k < (WARPS_PER_ROW * 32) / 16; ++k) {   // 8
            const float2 p = s_part[row][sub + k * 16];
            sq += p.x;
            sl += p.y;
        }

        #pragma unroll
        for (int off = 8; off > 0; off >>= 1) {
            sq += __shfl_down_sync(0xFFFFFFFFu, sq, off, 16);
            sl += __shfl_down_sync(0xFFFFFFFFu, sl, off, 16);
        }

        if (sub == 0) {
            const int orow = row0 + row;
            if (orow < B) {
                const float bias = *linb;
                out[orow] = fmaf(-sq, sq, sl + bias);
            }
        }
    }
}

extern "C" void kernel_launch(void* const* d_in, const int* in_sizes, int n_in,
                              void* d_out, int out_size)
{
    const float* inp  = (const float*)d_in[0];   // (B, D)
    const float* quad = (const float*)d_in[1];   // (D, 1)
    const float* linw = (const float*)d_in[2];   // (1, D)
    const float* linb = (const float*)d_in[3];   // (1,)
    float* out = (float*)d_out;

    const int B = in_sizes[0] / D_DIM;
    const int grid = (B + ROWS_PER_BLOCK - 1) / ROWS_PER_BLOCK;

    skinny_quad_kernel<<<grid, THREADS>>>(inp, quad, linw, linb, out, B);
}